// round 16
// baseline (speedup 1.0000x reference)
#include <cuda_runtime.h>
#include <cuda_bf16.h>
#include <mma.h>
#include <cstdint>
#include <cstddef>

using namespace nvcuda;

#define TT 511          // T-1 rows
#define VV 32000
#define EE 512
#define HH 512
#define SPLITS1 40      // split-K for GEMM1 (K=32000 -> 800 per split)
#define KSPLIT1 800

// ---------------- scratch (__device__ globals; no allocation) ----------------
__device__ float g_part[SPLITS1 * 512 * 512];
__device__ float g_emb[TT * EE];
__device__ float g_xproj[TT * HH];
__device__ float g_hs[512 * HH];                 // padded to 512 rows (row 511 = 0)
__device__ float g_logits[(size_t)512 * VV];     // padded to 512 rows for wmma store

// ---------------- f32x2 helpers (rnn) ----------------
__device__ __forceinline__ void fma2(unsigned long long& d, unsigned long long a,
                                     unsigned long long b) {
    asm("fma.rn.f32x2 %0, %1, %2, %0;" : "+l"(d) : "l"(a), "l"(b));
}
__device__ __forceinline__ float2 unpack2(unsigned long long d) {
    float2 r;
    asm("mov.b64 {%0, %1}, %2;" : "=f"(r.x), "=f"(r.y) : "l"(d));
    return r;
}

// ---------------- reduce split-K partials into emb ----------------
__global__ void reduce_emb_kernel()
{
    int i = blockIdx.x * 256 + threadIdx.x;
    if (i >= TT * EE) return;
    float s = 0.f;
#pragma unroll
    for (int p = 0; p < SPLITS1; p++) s += g_part[p * (512 * 512) + i];
    g_emb[i] = s;
}

// ---------------- xproj = emb @ W_x^T + b ----------------
__global__ void __launch_bounds__(256)
xproj_kernel(const float* __restrict__ W_x, const float* __restrict__ bias)
{
    __shared__ float As[16][68];
    __shared__ float Bs[16][68];
    const int tid = threadIdx.x;
    const int nt = blockIdx.x, mt = blockIdx.y;
    const int ty = tid >> 4, tx = tid & 15;
    const int m0 = ty * 4, n0 = tx * 4;
    float acc[4][4] = {};

    for (int kb = 0; kb < 512; kb += 16) {
        int m = tid >> 2, k4 = (tid & 3) << 2;
        float4 va = make_float4(0.f, 0.f, 0.f, 0.f);
        int ra = mt * 64 + m;
        if (ra < TT) va = *(const float4*)(g_emb + (size_t)ra * 512 + kb + k4);
        As[k4 + 0][m] = va.x; As[k4 + 1][m] = va.y;
        As[k4 + 2][m] = va.z; As[k4 + 3][m] = va.w;
        float4 vb = *(const float4*)(W_x + (size_t)(nt * 64 + m) * 512 + kb + k4);
        Bs[k4 + 0][m] = vb.x; Bs[k4 + 1][m] = vb.y;
        Bs[k4 + 2][m] = vb.z; Bs[k4 + 3][m] = vb.w;
        __syncthreads();
#pragma unroll
        for (int k = 0; k < 16; k++) {
            float4 a = *(const float4*)&As[k][m0];
            float4 b = *(const float4*)&Bs[k][n0];
            float aa[4] = {a.x, a.y, a.z, a.w};
            float bb[4] = {b.x, b.y, b.z, b.w};
#pragma unroll
            for (int i = 0; i < 4; i++)
#pragma unroll
                for (int j = 0; j < 4; j++) acc[i][j] += aa[i] * bb[j];
        }
        __syncthreads();
    }
#pragma unroll
    for (int i = 0; i < 4; i++) {
        int r = mt * 64 + m0 + i;
        if (r >= TT) continue;
#pragma unroll
        for (int j = 0; j < 4; j++) {
            int col = nt * 64 + n0 + j;
            g_xproj[(size_t)r * 512 + col] = acc[i][j] + bias[col];
        }
    }
}

// ---------------- Elman recurrence: R1 structure + SMEM xproj slice -------------
__global__ void __cluster_dims__(8, 1, 1) __launch_bounds__(1024, 1)
rnn_kernel(const float* __restrict__ W_h, int t0, int t1)
{
    extern __shared__ float xps[];                 // [(t1-t0) * 64]
    __shared__ float hbuf[2][512];
    __shared__ float pbuf[64][17];
    const int tid = threadIdx.x;
    const int w = tid >> 5, l = tid & 31;
    const int g = w & 1, s = w >> 1;
    const int c = (int)blockIdx.x;
    const int row = c * 64 + g * 32 + l;
    const int kbase = s * 32;

    ulonglong2 wv[8];
    {
        const ulonglong2* wp = (const ulonglong2*)(W_h + (size_t)row * 512 + kbase);
#pragma unroll
        for (int j = 0; j < 8; j++) wv[j] = wp[j];
    }
    for (int i = tid; i < 512; i += 1024)
        hbuf[0][i] = (t0 == 0) ? 0.f : g_hs[(size_t)(t0 - 1) * 512 + i];

    const int nloc = (t1 - t0) * 64;
    for (int i = tid; i < nloc; i += 1024)
        xps[i] = g_xproj[(size_t)(t0 + (i >> 6)) * 512 + c * 64 + (i & 63)];

    uint32_t hbase_local = (uint32_t)__cvta_generic_to_shared(&hbuf[0][0]);
    uint32_t peer[8];
#pragma unroll
    for (int p = 0; p < 8; p++)
        asm("mapa.shared::cluster.u32 %0, %1, %2;" : "=r"(peer[p]) : "r"(hbase_local), "r"(p));

    __syncthreads();
    asm volatile("barrier.cluster.arrive.aligned;" ::: "memory");
    asm volatile("barrier.cluster.wait.aligned;" ::: "memory");

    for (int t = t0; t < t1; t++) {
        const int cur = (t - t0) & 1;
        const ulonglong2* hp = (const ulonglong2*)&hbuf[cur][kbase];
        unsigned long long acc = 0ull;
#pragma unroll
        for (int j = 0; j < 8; j++) {
            ulonglong2 hh = hp[j];
            fma2(acc, wv[j].x, hh.x);
            fma2(acc, wv[j].y, hh.y);
        }
        float2 f = unpack2(acc);
        pbuf[g * 32 + l][s] = f.x + f.y;
        __syncthreads();
        if (tid < 64) {
            float x = xps[(t - t0) * 64 + tid];
#pragma unroll
            for (int s2 = 0; s2 < 16; s2++) x += pbuf[tid][s2];
            float h = 1.f / (1.f + __expf(-x));
            g_hs[(size_t)t * 512 + c * 64 + tid] = h;
            uint32_t off = (uint32_t)(((cur ^ 1) * 512 + c * 64 + tid) * 4);
#pragma unroll
            for (int p = 0; p < 8; p++)
                asm volatile("st.shared::cluster.f32 [%0], %1;"
                             :: "r"(peer[p] + off), "f"(h) : "memory");
        }
        asm volatile("barrier.cluster.arrive.aligned;" ::: "memory");
        asm volatile("barrier.cluster.wait.aligned;" ::: "memory");
    }
}

// ---------------- fused-split WMMA bf16 3-pass GEMM (fp32 inputs), occ 2 --------
// C[m,n] = sum_k A[m,k]*B[n,k], A,B fp32 K-major. Per 32-k chunk:
//   cp.async fp32 -> staging (2 bufs) -> convert (hi/lo bf16 split, identical
//   math to the old prep kernels) -> WMMA 3 passes (hh, hl, lh).
// CTA tile 128x128, 8 warps 2x4, warp tile 64x32. Dyn smem:
//   bf16 tiles Ah,Al,Bh,Bl 128x48  = 49152 B (single set)
//   fp32 staging 2 x (A 128x32 + B 128x32) = 65536 B
//   total 114688 B -> 2 CTAs/SM.
#define GF_LD 48
#define GF_TSZ (128 * GF_LD)                 // bf16 elems per tile
#define GF_STG (128 * 32)                    // floats per staging matrix
#define GF_SMEM (4 * GF_TSZ * 2 + 2 * 2 * GF_STG * 4)   // 114688 bytes

__device__ __forceinline__ void cp_async16(uint32_t dst, const void* src) {
    asm volatile("cp.async.cg.shared.global [%0], [%1], 16;"
                 :: "r"(dst), "l"(src));
}

__global__ void __launch_bounds__(256, 2)
gemm_wmma3f(const float* __restrict__ A, int lda,
            const float* __restrict__ B, int ldb,
            float* __restrict__ C, int ldc, size_t zStride, int kPerSplit,
            int mBase, int nBase)
{
    extern __shared__ __align__(16) unsigned char smraw[];
    __nv_bfloat16* tiles = (__nv_bfloat16*)smraw;               // Ah,Al,Bh,Bl
    float* stg = (float*)(smraw + 4 * GF_TSZ * 2);              // 2 x (A,B) fp32
    const uint32_t stg_base = (uint32_t)__cvta_generic_to_shared(stg);

    const int tid = threadIdx.x;
    const int wid = tid >> 5;
    const int warp_m = wid >> 2;          // 0..1
    const int warp_n = wid & 3;           // 0..3
    const int nt = blockIdx.x, mt = blockIdx.y, sz = blockIdx.z;
    const int arow = mBase + mt * 128, brow = (nBase + nt) * 128;
    const int kOff = sz * kPerSplit;
    const int nChunks = kPerSplit >> 5;
    float* Cz = C + (size_t)sz * zStride;

    // fill geometry: 128 rows x 8 segs (float4) = 1024 items / 256 thr = 4 each
    int it_r[4], it_seg[4];
#pragma unroll
    for (int i = 0; i < 4; i++) {
        int lin = tid + i * 256;
        it_r[i] = lin >> 3;
        it_seg[i] = lin & 7;
    }

    auto issue_chunk = [&](int buf, int kc) {
        uint32_t base = stg_base + (uint32_t)(buf * 2 * GF_STG) * 4;
#pragma unroll
        for (int i = 0; i < 4; i++) {
            int r = it_r[i], seg = it_seg[i];
            uint32_t off = (uint32_t)(r * 32 + seg * 4) * 4;
            cp_async16(base + off,
                       A + (size_t)(arow + r) * lda + kOff + kc + seg * 4);
            cp_async16(base + (uint32_t)GF_STG * 4 + off,
                       B + (size_t)(brow + r) * ldb + kOff + kc + seg * 4);
        }
        asm volatile("cp.async.commit_group;" ::: "memory");
    };

    auto convert_chunk = [&](int buf) {
        const float* Sa = stg + buf * 2 * GF_STG;
        const float* Sb = Sa + GF_STG;
#pragma unroll
        for (int i = 0; i < 4; i++) {
            int r = it_r[i], seg = it_seg[i];
            float4 va = *(const float4*)(Sa + r * 32 + seg * 4);
            float4 vb = *(const float4*)(Sb + r * 32 + seg * 4);
            float av[4] = {va.x, va.y, va.z, va.w};
            float bv[4] = {vb.x, vb.y, vb.z, vb.w};
            __nv_bfloat16 ah[4], al[4], bh[4], bl[4];
#pragma unroll
            for (int j = 0; j < 4; j++) {
                ah[j] = __float2bfloat16_rn(av[j]);
                al[j] = __float2bfloat16_rn(av[j] - __bfloat162float(ah[j]));
                bh[j] = __float2bfloat16_rn(bv[j]);
                bl[j] = __float2bfloat16_rn(bv[j] - __bfloat162float(bh[j]));
            }
            int e = r * GF_LD + seg * 4;
            *(__nv_bfloat162*)(tiles + 0 * GF_TSZ + e)     = __nv_bfloat162(ah[0], ah[1]);
            *(__nv_bfloat162*)(tiles + 0 * GF_TSZ + e + 2) = __nv_bfloat162(ah[2], ah[3]);
            *(__nv_bfloat162*)(tiles + 1 * GF_TSZ + e)     = __nv_bfloat162(al[0], al[1]);
            *(__nv_bfloat162*)(tiles + 1 * GF_TSZ + e + 2) = __nv_bfloat162(al[2], al[3]);
            *(__nv_bfloat162*)(tiles + 2 * GF_TSZ + e)     = __nv_bfloat162(bh[0], bh[1]);
            *(__nv_bfloat162*)(tiles + 2 * GF_TSZ + e + 2) = __nv_bfloat162(bh[2], bh[3]);
            *(__nv_bfloat162*)(tiles + 3 * GF_TSZ + e)     = __nv_bfloat162(bl[0], bl[1]);
            *(__nv_bfloat162*)(tiles + 3 * GF_TSZ + e + 2) = __nv_bfloat162(bl[2], bl[3]);
        }
    };

    wmma::fragment<wmma::accumulator, 16, 16, 16, float> acc[4][2];
#pragma unroll
    for (int mi = 0; mi < 4; mi++)
#pragma unroll
        for (int ni = 0; ni < 2; ni++) wmma::fill_fragment(acc[mi][ni], 0.f);

    issue_chunk(0, 0);
    if (nChunks > 1) issue_chunk(1, 32);

    for (int c = 0; c < nChunks; c++) {
        const int buf = c & 1;
        if (c + 2 < nChunks)
            asm volatile("cp.async.wait_group 1;" ::: "memory");
        else
            asm volatile("cp.async.wait_group 0;" ::: "memory");
        __syncthreads();                 // staging[buf] visible
        convert_chunk(buf);
        __syncthreads();                 // bf16 tiles ready; staging[buf] free
        if (c + 2 < nChunks)
            issue_chunk(buf, (c + 2) * 32);

#pragma unroll
        for (int kk = 0; kk < 2; kk++) {
            const int k0 = kk * 16;
#pragma unroll
            for (int p = 0; p < 3; p++) {           // (hi,hi), (hi,lo), (lo,hi)
                const int pa = (p == 2) ? 1 : 0;
                const int pb = (p == 1) ? 1 : 0;
                wmma::fragment<wmma::matrix_a, 16, 16, 16, __nv_bfloat16, wmma::row_major> af[4];
                wmma::fragment<wmma::matrix_b, 16, 16, 16, __nv_bfloat16, wmma::col_major> bf[2];
#pragma unroll
                for (int mi = 0; mi < 4; mi++)
                    wmma::load_matrix_sync(af[mi],
                        tiles + pa * GF_TSZ + (warp_m * 64 + mi * 16) * GF_LD + k0, GF_LD);
#pragma unroll
                for (int ni = 0; ni < 2; ni++)
                    wmma::load_matrix_sync(bf[ni],
                        tiles + (2 + pb) * GF_TSZ + (warp_n * 32 + ni * 16) * GF_LD + k0, GF_LD);
#pragma unroll
                for (int mi = 0; mi < 4; mi++)
#pragma unroll
                    for (int ni = 0; ni < 2; ni++)
                        wmma::mma_sync(acc[mi][ni], af[mi], bf[ni], acc[mi][ni]);
            }
        }
        __syncthreads();                 // compute done before next convert
    }

#pragma unroll
    for (int mi = 0; mi < 4; mi++)
#pragma unroll
        for (int ni = 0; ni < 2; ni++) {
            int m = arow + warp_m * 64 + mi * 16;
            int n = brow + warp_n * 32 + ni * 16;
            wmma::store_matrix_sync(Cz + (size_t)m * ldc + n, acc[mi][ni], ldc,
                                    wmma::mem_row_major);
        }
}

// ---------------- fused single-pass row softmax over V=32000 ----------------
__global__ void __launch_bounds__(512)
softmax_kernel(float* __restrict__ out, int rowBase)
{
    extern __shared__ float buf[];                     // 32000 floats
    __shared__ float red[512];
    const int t = rowBase + blockIdx.x;
    const int tid = threadIdx.x;
    const float4* r4 = (const float4*)(g_logits + (size_t)t * VV);
    float4* b4 = (float4*)buf;
    float4* o4 = (float4*)(out + (size_t)t * VV);

    float mx = -3.402823466e38f;
    for (int i = tid; i < VV / 4; i += 512) {
        float4 v = r4[i];
        b4[i] = v;
        mx = fmaxf(mx, fmaxf(fmaxf(v.x, v.y), fmaxf(v.z, v.w)));
    }
    red[tid] = mx; __syncthreads();
    for (int o = 256; o > 0; o >>= 1) {
        if (tid < o) red[tid] = fmaxf(red[tid], red[tid + o]);
        __syncthreads();
    }
    mx = red[0]; __syncthreads();

    float sum = 0.f;
    for (int i = tid; i < VV / 4; i += 512) {
        float4 v = b4[i];
        v.x = __expf(v.x - mx); v.y = __expf(v.y - mx);
        v.z = __expf(v.z - mx); v.w = __expf(v.w - mx);
        b4[i] = v;
        sum += (v.x + v.y) + (v.z + v.w);
    }
    red[tid] = sum; __syncthreads();
    for (int o = 256; o > 0; o >>= 1) {
        if (tid < o) red[tid] += red[tid + o];
        __syncthreads();
    }
    float inv = 1.f / red[0];

    for (int i = tid; i < VV / 4; i += 512) {
        float4 v = b4[i];
        v.x *= inv; v.y *= inv; v.z *= inv; v.w *= inv;
        o4[i] = v;
    }
}

// ---------------- launch: rnn pipelined against gemm2/softmax tiles -------------
extern "C" void kernel_launch(void* const* d_in, const int* in_sizes, int n_in,
                              void* d_out, int out_size)
{
    const float* sent = (const float*)d_in[0];
    const float* W_e  = (const float*)d_in[1];
    const float* W_x  = (const float*)d_in[2];
    const float* W_h  = (const float*)d_in[3];
    const float* W_p  = (const float*)d_in[4];
    const float* b    = (const float*)d_in[5];
    float* out = (float*)d_out;

    float *part, *logits, *hs_ptr;
    cudaGetSymbolAddress((void**)&part,   g_part);
    cudaGetSymbolAddress((void**)&logits, g_logits);
    cudaGetSymbolAddress((void**)&hs_ptr, g_hs);

    cudaFuncSetAttribute(softmax_kernel,
                         cudaFuncAttributeMaxDynamicSharedMemorySize, VV * 4);
    cudaFuncSetAttribute(gemm_wmma3f,
                         cudaFuncAttributeMaxDynamicSharedMemorySize, GF_SMEM);
    cudaFuncSetAttribute(rnn_kernel,
                         cudaFuncAttributeMaxDynamicSharedMemorySize, 128 * 64 * 4);

    // side stream + events, created ONCE
    static cudaStream_t side = nullptr;
    static cudaEvent_t evp[4], evj = nullptr;
    if (!side) {
        cudaStreamCreateWithFlags(&side, cudaStreamNonBlocking);
        for (int m = 0; m < 4; m++)
            cudaEventCreateWithFlags(&evp[m], cudaEventDisableTiming);
        cudaEventCreateWithFlags(&evj, cudaEventDisableTiming);
    }

    // main chain: gemm1 reads fp32 sent/W_e directly (fused split — no prep)
    gemm_wmma3f<<<dim3(4, 4, SPLITS1), 256, GF_SMEM>>>(
        sent, VV, W_e, VV, part, 512, (size_t)512 * 512, KSPLIT1, 0, 0);
    reduce_emb_kernel<<<(TT * EE + 255) / 256, 256>>>();
    xproj_kernel<<<dim3(8, 8), 256>>>(W_x, b);

    // rnn parts pipelined against per-tile gemm2 + softmax on side stream
    const int bounds[5] = {0, 128, 256, 384, TT};
    for (int m = 0; m < 4; m++) {
        int len = bounds[m + 1] - bounds[m];
        rnn_kernel<<<8, 1024, len * 64 * 4>>>(W_h, bounds[m], bounds[m + 1]);
        cudaEventRecord(evp[m], 0);
        cudaStreamWaitEvent(side, evp[m], 0);
        gemm_wmma3f<<<dim3(125, 1, 1), 256, GF_SMEM, side>>>(
            hs_ptr, 512, W_p, 512, logits, VV, 0, 512, m * 128, 0);
        gemm_wmma3f<<<dim3(125, 1, 1), 256, GF_SMEM, side>>>(
            hs_ptr, 512, W_p, 512, logits, VV, 0, 512, m * 128, 125);
        softmax_kernel<<<len, 512, VV * 4, side>>>(out, bounds[m]);
    }

    // join side stream back into the main (capture) stream
    cudaEventRecord(evj, side);
    cudaStreamWaitEvent(0, evj, 0);
}

// round 17
// speedup vs baseline: 1.2034x; 1.2034x over previous
#include <cuda_runtime.h>
#include <cuda_bf16.h>
#include <mma.h>
#include <cstdint>
#include <cstddef>

using namespace nvcuda;

#define TT 511          // T-1 rows
#define VV 32000
#define EE 512
#define HH 512
#define SPLITS1 40      // split-K for GEMM1 (K=32000 -> 800 per split)
#define KSPLIT1 800

// ---------------- scratch (__device__ globals; no allocation) ----------------
__device__ float g_part[SPLITS1 * 512 * 512];
__device__ float g_emb[TT * EE];
__device__ float g_xproj[TT * HH];
__device__ float g_hs[512 * HH];                 // padded to 512 rows
__device__ float g_logits[(size_t)512 * VV];     // padded to 512 rows

// ---------------- f32x2 helpers (rnn) ----------------
__device__ __forceinline__ void fma2(unsigned long long& d, unsigned long long a,
                                     unsigned long long b) {
    asm("fma.rn.f32x2 %0, %1, %2, %0;" : "+l"(d) : "l"(a), "l"(b));
}
__device__ __forceinline__ float2 unpack2(unsigned long long d) {
    float2 r;
    asm("mov.b64 {%0, %1}, %2;" : "=f"(r.x), "=f"(r.y) : "l"(d));
    return r;
}

// ---------------- reduce split-K partials into emb (128-row tile) ----------------
__global__ void reduce_emb_kernel(int rowBase)
{
    int i = blockIdx.x * 256 + threadIdx.x;       // 0 .. 128*512-1
    if (i >= 128 * 512) return;
    int row = rowBase + (i >> 9);
    if (row >= TT) return;
    int idx = rowBase * 512 + i;
    float s = 0.f;
#pragma unroll
    for (int p = 0; p < SPLITS1; p++) s += g_part[p * (512 * 512) + idx];
    g_emb[idx] = s;
}

// ---------------- xproj = emb @ W_x^T + b (two 64-row tiles per call) ------------
__global__ void __launch_bounds__(256)
xproj_kernel(const float* __restrict__ W_x, const float* __restrict__ bias,
             int mtBase)
{
    __shared__ float As[16][68];
    __shared__ float Bs[16][68];
    const int tid = threadIdx.x;
    const int nt = blockIdx.x, mt = mtBase + blockIdx.y;
    const int ty = tid >> 4, tx = tid & 15;
    const int m0 = ty * 4, n0 = tx * 4;
    float acc[4][4] = {};

    for (int kb = 0; kb < 512; kb += 16) {
        int m = tid >> 2, k4 = (tid & 3) << 2;
        float4 va = make_float4(0.f, 0.f, 0.f, 0.f);
        int ra = mt * 64 + m;
        if (ra < TT) va = *(const float4*)(g_emb + (size_t)ra * 512 + kb + k4);
        As[k4 + 0][m] = va.x; As[k4 + 1][m] = va.y;
        As[k4 + 2][m] = va.z; As[k4 + 3][m] = va.w;
        float4 vb = *(const float4*)(W_x + (size_t)(nt * 64 + m) * 512 + kb + k4);
        Bs[k4 + 0][m] = vb.x; Bs[k4 + 1][m] = vb.y;
        Bs[k4 + 2][m] = vb.z; Bs[k4 + 3][m] = vb.w;
        __syncthreads();
#pragma unroll
        for (int k = 0; k < 16; k++) {
            float4 a = *(const float4*)&As[k][m0];
            float4 b = *(const float4*)&Bs[k][n0];
            float aa[4] = {a.x, a.y, a.z, a.w};
            float bb[4] = {b.x, b.y, b.z, b.w};
#pragma unroll
            for (int i = 0; i < 4; i++)
#pragma unroll
                for (int j = 0; j < 4; j++) acc[i][j] += aa[i] * bb[j];
        }
        __syncthreads();
    }
#pragma unroll
    for (int i = 0; i < 4; i++) {
        int r = mt * 64 + m0 + i;
        if (r >= TT) continue;
#pragma unroll
        for (int j = 0; j < 4; j++) {
            int col = nt * 64 + n0 + j;
            g_xproj[(size_t)r * 512 + col] = acc[i][j] + bias[col];
        }
    }
}

// ---------------- Elman recurrence: R1 structure + SMEM xproj slice -------------
__global__ void __cluster_dims__(8, 1, 1) __launch_bounds__(1024, 1)
rnn_kernel(const float* __restrict__ W_h, int t0, int t1)
{
    extern __shared__ float xps[];                 // [(t1-t0) * 64]
    __shared__ float hbuf[2][512];
    __shared__ float pbuf[64][17];
    const int tid = threadIdx.x;
    const int w = tid >> 5, l = tid & 31;
    const int g = w & 1, s = w >> 1;
    const int c = (int)blockIdx.x;
    const int row = c * 64 + g * 32 + l;
    const int kbase = s * 32;

    ulonglong2 wv[8];
    {
        const ulonglong2* wp = (const ulonglong2*)(W_h + (size_t)row * 512 + kbase);
#pragma unroll
        for (int j = 0; j < 8; j++) wv[j] = wp[j];
    }
    for (int i = tid; i < 512; i += 1024)
        hbuf[0][i] = (t0 == 0) ? 0.f : g_hs[(size_t)(t0 - 1) * 512 + i];

    const int nloc = (t1 - t0) * 64;
    for (int i = tid; i < nloc; i += 1024)
        xps[i] = g_xproj[(size_t)(t0 + (i >> 6)) * 512 + c * 64 + (i & 63)];

    uint32_t hbase_local = (uint32_t)__cvta_generic_to_shared(&hbuf[0][0]);
    uint32_t peer[8];
#pragma unroll
    for (int p = 0; p < 8; p++)
        asm("mapa.shared::cluster.u32 %0, %1, %2;" : "=r"(peer[p]) : "r"(hbase_local), "r"(p));

    __syncthreads();
    asm volatile("barrier.cluster.arrive.aligned;" ::: "memory");
    asm volatile("barrier.cluster.wait.aligned;" ::: "memory");

    for (int t = t0; t < t1; t++) {
        const int cur = (t - t0) & 1;
        const ulonglong2* hp = (const ulonglong2*)&hbuf[cur][kbase];
        unsigned long long acc = 0ull;
#pragma unroll
        for (int j = 0; j < 8; j++) {
            ulonglong2 hh = hp[j];
            fma2(acc, wv[j].x, hh.x);
            fma2(acc, wv[j].y, hh.y);
        }
        float2 f = unpack2(acc);
        pbuf[g * 32 + l][s] = f.x + f.y;
        __syncthreads();
        if (tid < 64) {
            float x = xps[(t - t0) * 64 + tid];
#pragma unroll
            for (int s2 = 0; s2 < 16; s2++) x += pbuf[tid][s2];
            float h = 1.f / (1.f + __expf(-x));
            g_hs[(size_t)t * 512 + c * 64 + tid] = h;
            uint32_t off = (uint32_t)(((cur ^ 1) * 512 + c * 64 + tid) * 4);
#pragma unroll
            for (int p = 0; p < 8; p++)
                asm volatile("st.shared::cluster.f32 [%0], %1;"
                             :: "r"(peer[p] + off), "f"(h) : "memory");
        }
        asm volatile("barrier.cluster.arrive.aligned;" ::: "memory");
        asm volatile("barrier.cluster.wait.aligned;" ::: "memory");
    }
}

// ---------------- fused-split WMMA bf16 3-pass GEMM (fp32 inputs), occ 2 --------
#define GF_LD 48
#define GF_TSZ (128 * GF_LD)                 // bf16 elems per tile
#define GF_STG (128 * 32)                    // floats per staging matrix
#define GF_SMEM (4 * GF_TSZ * 2 + 2 * 2 * GF_STG * 4)   // 114688 bytes

__device__ __forceinline__ void cp_async16(uint32_t dst, const void* src) {
    asm volatile("cp.async.cg.shared.global [%0], [%1], 16;"
                 :: "r"(dst), "l"(src));
}

__global__ void __launch_bounds__(256, 2)
gemm_wmma3f(const float* __restrict__ A, int lda,
            const float* __restrict__ B, int ldb,
            float* __restrict__ C, int ldc, size_t zStride, int kPerSplit,
            int mBase, int nBase)
{
    extern __shared__ __align__(16) unsigned char smraw[];
    __nv_bfloat16* tiles = (__nv_bfloat16*)smraw;               // Ah,Al,Bh,Bl
    float* stg = (float*)(smraw + 4 * GF_TSZ * 2);              // 2 x (A,B) fp32
    const uint32_t stg_base = (uint32_t)__cvta_generic_to_shared(stg);

    const int tid = threadIdx.x;
    const int wid = tid >> 5;
    const int warp_m = wid >> 2;          // 0..1
    const int warp_n = wid & 3;           // 0..3
    const int nt = blockIdx.x, mt = blockIdx.y, sz = blockIdx.z;
    const int arow = mBase + mt * 128, brow = (nBase + nt) * 128;
    const int kOff = sz * kPerSplit;
    const int nChunks = kPerSplit >> 5;
    float* Cz = C + (size_t)sz * zStride;

    int it_r[4], it_seg[4];
#pragma unroll
    for (int i = 0; i < 4; i++) {
        int lin = tid + i * 256;
        it_r[i] = lin >> 3;
        it_seg[i] = lin & 7;
    }

    auto issue_chunk = [&](int buf, int kc) {
        uint32_t base = stg_base + (uint32_t)(buf * 2 * GF_STG) * 4;
#pragma unroll
        for (int i = 0; i < 4; i++) {
            int r = it_r[i], seg = it_seg[i];
            uint32_t off = (uint32_t)(r * 32 + seg * 4) * 4;
            cp_async16(base + off,
                       A + (size_t)(arow + r) * lda + kOff + kc + seg * 4);
            cp_async16(base + (uint32_t)GF_STG * 4 + off,
                       B + (size_t)(brow + r) * ldb + kOff + kc + seg * 4);
        }
        asm volatile("cp.async.commit_group;" ::: "memory");
    };

    auto convert_chunk = [&](int buf) {
        const float* Sa = stg + buf * 2 * GF_STG;
        const float* Sb = Sa + GF_STG;
#pragma unroll
        for (int i = 0; i < 4; i++) {
            int r = it_r[i], seg = it_seg[i];
            float4 va = *(const float4*)(Sa + r * 32 + seg * 4);
            float4 vb = *(const float4*)(Sb + r * 32 + seg * 4);
            float av[4] = {va.x, va.y, va.z, va.w};
            float bv[4] = {vb.x, vb.y, vb.z, vb.w};
            __nv_bfloat16 ah[4], al[4], bh[4], bl[4];
#pragma unroll
            for (int j = 0; j < 4; j++) {
                ah[j] = __float2bfloat16_rn(av[j]);
                al[j] = __float2bfloat16_rn(av[j] - __bfloat162float(ah[j]));
                bh[j] = __float2bfloat16_rn(bv[j]);
                bl[j] = __float2bfloat16_rn(bv[j] - __bfloat162float(bh[j]));
            }
            int e = r * GF_LD + seg * 4;
            *(__nv_bfloat162*)(tiles + 0 * GF_TSZ + e)     = __nv_bfloat162(ah[0], ah[1]);
            *(__nv_bfloat162*)(tiles + 0 * GF_TSZ + e + 2) = __nv_bfloat162(ah[2], ah[3]);
            *(__nv_bfloat162*)(tiles + 1 * GF_TSZ + e)     = __nv_bfloat162(al[0], al[1]);
            *(__nv_bfloat162*)(tiles + 1 * GF_TSZ + e + 2) = __nv_bfloat162(al[2], al[3]);
            *(__nv_bfloat162*)(tiles + 2 * GF_TSZ + e)     = __nv_bfloat162(bh[0], bh[1]);
            *(__nv_bfloat162*)(tiles + 2 * GF_TSZ + e + 2) = __nv_bfloat162(bh[2], bh[3]);
            *(__nv_bfloat162*)(tiles + 3 * GF_TSZ + e)     = __nv_bfloat162(bl[0], bl[1]);
            *(__nv_bfloat162*)(tiles + 3 * GF_TSZ + e + 2) = __nv_bfloat162(bl[2], bl[3]);
        }
    };

    wmma::fragment<wmma::accumulator, 16, 16, 16, float> acc[4][2];
#pragma unroll
    for (int mi = 0; mi < 4; mi++)
#pragma unroll
        for (int ni = 0; ni < 2; ni++) wmma::fill_fragment(acc[mi][ni], 0.f);

    issue_chunk(0, 0);
    if (nChunks > 1) issue_chunk(1, 32);

    for (int c = 0; c < nChunks; c++) {
        const int buf = c & 1;
        if (c + 2 < nChunks)
            asm volatile("cp.async.wait_group 1;" ::: "memory");
        else
            asm volatile("cp.async.wait_group 0;" ::: "memory");
        __syncthreads();
        convert_chunk(buf);
        __syncthreads();
        if (c + 2 < nChunks)
            issue_chunk(buf, (c + 2) * 32);

#pragma unroll
        for (int kk = 0; kk < 2; kk++) {
            const int k0 = kk * 16;
#pragma unroll
            for (int p = 0; p < 3; p++) {           // (hi,hi), (hi,lo), (lo,hi)
                const int pa = (p == 2) ? 1 : 0;
                const int pb = (p == 1) ? 1 : 0;
                wmma::fragment<wmma::matrix_a, 16, 16, 16, __nv_bfloat16, wmma::row_major> af[4];
                wmma::fragment<wmma::matrix_b, 16, 16, 16, __nv_bfloat16, wmma::col_major> bf[2];
#pragma unroll
                for (int mi = 0; mi < 4; mi++)
                    wmma::load_matrix_sync(af[mi],
                        tiles + pa * GF_TSZ + (warp_m * 64 + mi * 16) * GF_LD + k0, GF_LD);
#pragma unroll
                for (int ni = 0; ni < 2; ni++)
                    wmma::load_matrix_sync(bf[ni],
                        tiles + (2 + pb) * GF_TSZ + (warp_n * 32 + ni * 16) * GF_LD + k0, GF_LD);
#pragma unroll
                for (int mi = 0; mi < 4; mi++)
#pragma unroll
                    for (int ni = 0; ni < 2; ni++)
                        wmma::mma_sync(acc[mi][ni], af[mi], bf[ni], acc[mi][ni]);
            }
        }
        __syncthreads();
    }

#pragma unroll
    for (int mi = 0; mi < 4; mi++)
#pragma unroll
        for (int ni = 0; ni < 2; ni++) {
            int m = arow + warp_m * 64 + mi * 16;
            int n = brow + warp_n * 32 + ni * 16;
            wmma::store_matrix_sync(Cz + (size_t)m * ldc + n, acc[mi][ni], ldc,
                                    wmma::mem_row_major);
        }
}

// ---------------- fused single-pass row softmax over V=32000 ----------------
__global__ void __launch_bounds__(512)
softmax_kernel(float* __restrict__ out, int rowBase)
{
    extern __shared__ float buf[];                     // 32000 floats
    __shared__ float red[512];
    const int t = rowBase + blockIdx.x;
    const int tid = threadIdx.x;
    const float4* r4 = (const float4*)(g_logits + (size_t)t * VV);
    float4* b4 = (float4*)buf;
    float4* o4 = (float4*)(out + (size_t)t * VV);

    float mx = -3.402823466e38f;
    for (int i = tid; i < VV / 4; i += 512) {
        float4 v = r4[i];
        b4[i] = v;
        mx = fmaxf(mx, fmaxf(fmaxf(v.x, v.y), fmaxf(v.z, v.w)));
    }
    red[tid] = mx; __syncthreads();
    for (int o = 256; o > 0; o >>= 1) {
        if (tid < o) red[tid] = fmaxf(red[tid], red[tid + o]);
        __syncthreads();
    }
    mx = red[0]; __syncthreads();

    float sum = 0.f;
    for (int i = tid; i < VV / 4; i += 512) {
        float4 v = b4[i];
        v.x = __expf(v.x - mx); v.y = __expf(v.y - mx);
        v.z = __expf(v.z - mx); v.w = __expf(v.w - mx);
        b4[i] = v;
        sum += (v.x + v.y) + (v.z + v.w);
    }
    red[tid] = sum; __syncthreads();
    for (int o = 256; o > 0; o >>= 1) {
        if (tid < o) red[tid] += red[tid + o];
        __syncthreads();
    }
    float inv = 1.f / red[0];

    for (int i = tid; i < VV / 4; i += 512) {
        float4 v = b4[i];
        v.x *= inv; v.y *= inv; v.z *= inv; v.w *= inv;
        o4[i] = v;
    }
}

// ---------------- launch: M-tiled producer pipeline --------------------------
// main:  g1(tile0) -> reduce0 -> xproj0 -> rnn0..rnn3 (rnn m>0 gated by evx[m])
// side:  (after xproj0) g1(tile m)->reduce->xproj->evx[m] for m=1..3;
//        then per evr[m]: gemm2(tile m) x2 -> softmax(tile m)
extern "C" void kernel_launch(void* const* d_in, const int* in_sizes, int n_in,
                              void* d_out, int out_size)
{
    const float* sent = (const float*)d_in[0];
    const float* W_e  = (const float*)d_in[1];
    const float* W_x  = (const float*)d_in[2];
    const float* W_h  = (const float*)d_in[3];
    const float* W_p  = (const float*)d_in[4];
    const float* b    = (const float*)d_in[5];
    float* out = (float*)d_out;

    float *part, *logits, *hs_ptr;
    cudaGetSymbolAddress((void**)&part,   g_part);
    cudaGetSymbolAddress((void**)&logits, g_logits);
    cudaGetSymbolAddress((void**)&hs_ptr, g_hs);

    cudaFuncSetAttribute(softmax_kernel,
                         cudaFuncAttributeMaxDynamicSharedMemorySize, VV * 4);
    cudaFuncSetAttribute(gemm_wmma3f,
                         cudaFuncAttributeMaxDynamicSharedMemorySize, GF_SMEM);
    cudaFuncSetAttribute(rnn_kernel,
                         cudaFuncAttributeMaxDynamicSharedMemorySize, 128 * 64 * 4);

    static cudaStream_t side = nullptr;
    static cudaEvent_t evf = nullptr, evx[4], evr[4], evj = nullptr;
    if (!side) {
        cudaStreamCreateWithFlags(&side, cudaStreamNonBlocking);
        cudaEventCreateWithFlags(&evf, cudaEventDisableTiming);
        for (int m = 0; m < 4; m++) {
            cudaEventCreateWithFlags(&evx[m], cudaEventDisableTiming);
            cudaEventCreateWithFlags(&evr[m], cudaEventDisableTiming);
        }
        cudaEventCreateWithFlags(&evj, cudaEventDisableTiming);
    }

    const int bounds[5] = {0, 128, 256, 384, TT};

    // ---- main: tile-0 producer chain (full chip), then rnn chain ----
    gemm_wmma3f<<<dim3(4, 1, SPLITS1), 256, GF_SMEM>>>(
        sent, VV, W_e, VV, part, 512, (size_t)512 * 512, KSPLIT1, 0, 0);
    reduce_emb_kernel<<<256, 256>>>(0);
    xproj_kernel<<<dim3(8, 2), 256>>>(W_x, b, 0);
    cudaEventRecord(evf, 0);                     // fork point for side producers
    cudaStreamWaitEvent(side, evf, 0);

    // ---- side: producer chain for tiles 1..3 ----
    for (int m = 1; m < 4; m++) {
        gemm_wmma3f<<<dim3(4, 1, SPLITS1), 256, GF_SMEM, side>>>(
            sent, VV, W_e, VV, part, 512, (size_t)512 * 512, KSPLIT1, m * 128, 0);
        reduce_emb_kernel<<<256, 256, 0, side>>>(m * 128);
        xproj_kernel<<<dim3(8, 2), 256, 0, side>>>(W_x, b, m * 2);
        cudaEventRecord(evx[m], side);
    }

    // ---- main: rnn chain; side: consumer chain per finished part ----
    for (int m = 0; m < 4; m++) {
        if (m > 0) cudaStreamWaitEvent(0, evx[m], 0);
        int len = bounds[m + 1] - bounds[m];
        rnn_kernel<<<8, 1024, len * 64 * 4>>>(W_h, bounds[m], bounds[m + 1]);
        cudaEventRecord(evr[m], 0);
    }
    for (int m = 0; m < 4; m++) {
        cudaStreamWaitEvent(side, evr[m], 0);
        int len = bounds[m + 1] - bounds[m];
        gemm_wmma3f<<<dim3(125, 1, 1), 256, GF_SMEM, side>>>(
            hs_ptr, 512, W_p, 512, logits, VV, 0, 512, m * 128, 0);
        gemm_wmma3f<<<dim3(125, 1, 1), 256, GF_SMEM, side>>>(
            hs_ptr, 512, W_p, 512, logits, VV, 0, 512, m * 128, 125);
        softmax_kernel<<<len, 512, VV * 4, side>>>(out, bounds[m]);
    }

    cudaEventRecord(evj, side);
    cudaStreamWaitEvent(0, evj, 0);
}